// round 1
// baseline (speedup 1.0000x reference)
#include <cuda_runtime.h>
#include <cstdint>

// Problem constants
#define BB 2
#define TT 2048
#define DD 1024
#define NH 16
#define DH 64
#define BT (BB*TT)   // 4096

// Scratch (device globals — no allocation allowed)
__device__ float g_q[BT * DD];
__device__ float g_k[BT * DD];
__device__ float g_v[BT * DD];
__device__ float g_o[BT * DD];

// ---------------------------------------------------------------------------
// SGEMM: C[4096,1024] = A[4096,1024] @ W[1024,1024], fp32, 128x128x16 tiles,
// 256 threads, 8x8 register blocking.
// ---------------------------------------------------------------------------
__device__ __forceinline__ void sgemm_body(const float* __restrict__ A,
                                           const float* __restrict__ W,
                                           float* __restrict__ C) {
    constexpr int N = 1024, K = 1024;
    __shared__ float As[16][132];   // A tile transposed, padded (store-conflict relief)
    __shared__ float Bs[16][128];

    const int tid = threadIdx.x;
    const int tx = tid & 15;
    const int ty = tid >> 4;
    const int rowBase = blockIdx.y * 128;
    const int colBase = blockIdx.x * 128;

    float acc[8][8];
#pragma unroll
    for (int i = 0; i < 8; i++)
#pragma unroll
        for (int j = 0; j < 8; j++) acc[i][j] = 0.f;

    for (int k0 = 0; k0 < K; k0 += 16) {
        // Load A tile (128x16), store transposed: As[c][r]
#pragma unroll
        for (int it = 0; it < 2; it++) {
            int idx = tid + it * 256;        // 0..511, 4 floats each
            int r = idx >> 2;                // 0..127
            int c = (idx & 3) << 2;          // 0,4,8,12
            float4 v = *(const float4*)&A[(size_t)(rowBase + r) * K + k0 + c];
            As[c + 0][r] = v.x;
            As[c + 1][r] = v.y;
            As[c + 2][r] = v.z;
            As[c + 3][r] = v.w;
        }
        // Load B tile (16x128) row-major
#pragma unroll
        for (int it = 0; it < 2; it++) {
            int idx = tid + it * 256;
            int r = idx >> 5;                // 0..15
            int c = (idx & 31) << 2;         // 0..124
            *(float4*)&Bs[r][c] = *(const float4*)&W[(size_t)(k0 + r) * N + colBase + c];
        }
        __syncthreads();

#pragma unroll
        for (int kk = 0; kk < 16; kk++) {
            float a[8], b[8];
            *(float4*)&a[0] = *(float4*)&As[kk][ty * 8];
            *(float4*)&a[4] = *(float4*)&As[kk][ty * 8 + 4];
            *(float4*)&b[0] = *(float4*)&Bs[kk][tx * 8];
            *(float4*)&b[4] = *(float4*)&Bs[kk][tx * 8 + 4];
#pragma unroll
            for (int i = 0; i < 8; i++)
#pragma unroll
                for (int j = 0; j < 8; j++)
                    acc[i][j] = fmaf(a[i], b[j], acc[i][j]);
        }
        __syncthreads();
    }

#pragma unroll
    for (int i = 0; i < 8; i++) {
        size_t r = (size_t)(rowBase + ty * 8 + i);
#pragma unroll
        for (int j = 0; j < 8; j += 4) {
            float4 v = make_float4(acc[i][j], acc[i][j + 1], acc[i][j + 2], acc[i][j + 3]);
            *(float4*)&C[r * N + colBase + tx * 8 + j] = v;
        }
    }
}

__global__ __launch_bounds__(256, 2) void qkv_kernel(const float* __restrict__ X,
                                                     const float* __restrict__ Wq,
                                                     const float* __restrict__ Wk,
                                                     const float* __restrict__ Wv) {
    const float* W = (blockIdx.z == 0) ? Wq : ((blockIdx.z == 1) ? Wk : Wv);
    float* C = (blockIdx.z == 0) ? g_q : ((blockIdx.z == 1) ? g_k : g_v);
    sgemm_body(X, W, C);
}

__global__ __launch_bounds__(256, 2) void out_kernel(const float* __restrict__ Wo,
                                                     float* __restrict__ out) {
    sgemm_body(g_o, Wo, out);
}

// ---------------------------------------------------------------------------
// Flash attention (causal), fp32. Block = 64 query rows for one (b, h).
// 256 threads: 16x16 thread grid, each thread owns a 4x4 tile of S / O.
// Static shared = exactly 48KB (Qts + KV union + Pts, all 64x64 fp32).
// Layouts chosen so every compute-phase smem read is a conflict-free float4:
//   Qts[d][r]  (d-major), K in KVs[d][c] (d-major), V in KVs[c][d] (natural),
//   Pts[c][r]  (c-major).
// ---------------------------------------------------------------------------
__global__ __launch_bounds__(256) void flash_kernel() {
    __shared__ float Qts[64 * 64];
    __shared__ float KVs[64 * 64];
    __shared__ float Pts[64 * 64];

    const int tid = threadIdx.x;
    const int tx = tid & 15;     // col group
    const int ty = tid >> 4;     // row group
    const int qt = blockIdx.x;   // q tile 0..31
    const int h  = blockIdx.y;
    const int b  = blockIdx.z;
    const int qbase = qt * 64;
    const float scale = 0.125f;  // 1/sqrt(64)

    const size_t headOff = (size_t)b * TT * DD + (size_t)h * DH;
    const float* Qg = g_q + headOff;
    const float* Kg = g_k + headOff;
    const float* Vg = g_v + headOff;
    float* Og = g_o + headOff;

    // Load Q tile, transposed + pre-scaled: Qts[d][r]
    for (int idx = tid; idx < 1024; idx += 256) {
        int r  = idx >> 4;
        int c4 = (idx & 15) << 2;
        float4 v = *(const float4*)&Qg[(size_t)(qbase + r) * DD + c4];
        Qts[(c4 + 0) * 64 + r] = v.x * scale;
        Qts[(c4 + 1) * 64 + r] = v.y * scale;
        Qts[(c4 + 2) * 64 + r] = v.z * scale;
        Qts[(c4 + 3) * 64 + r] = v.w * scale;
    }

    float m[4], l[4], o[4][4];
#pragma unroll
    for (int i = 0; i < 4; i++) {
        m[i] = -1e30f;
        l[i] = 0.f;
#pragma unroll
        for (int j = 0; j < 4; j++) o[i][j] = 0.f;
    }

    for (int jt = 0; jt <= qt; jt++) {
        const int kbase = jt * 64;

        __syncthreads();  // KVs/Pts free; also covers Q load on first iter

        // Load K tile transposed: KVs[d][c]
        for (int idx = tid; idx < 1024; idx += 256) {
            int r  = idx >> 4;
            int c4 = (idx & 15) << 2;
            float4 v = *(const float4*)&Kg[(size_t)(kbase + r) * DD + c4];
            KVs[(c4 + 0) * 64 + r] = v.x;
            KVs[(c4 + 1) * 64 + r] = v.y;
            KVs[(c4 + 2) * 64 + r] = v.z;
            KVs[(c4 + 3) * 64 + r] = v.w;
        }
        __syncthreads();

        // S[i][j] = sum_d Q[r_i][d] * K[c_j][d]
        float s[4][4];
#pragma unroll
        for (int i = 0; i < 4; i++)
#pragma unroll
            for (int j = 0; j < 4; j++) s[i][j] = 0.f;

#pragma unroll 8
        for (int d = 0; d < 64; d++) {
            float4 a4 = *(float4*)&Qts[d * 64 + ty * 4];
            float4 b4 = *(float4*)&KVs[d * 64 + tx * 4];
            float av[4] = {a4.x, a4.y, a4.z, a4.w};
            float bv[4] = {b4.x, b4.y, b4.z, b4.w};
#pragma unroll
            for (int i = 0; i < 4; i++)
#pragma unroll
                for (int j = 0; j < 4; j++)
                    s[i][j] = fmaf(av[i], bv[j], s[i][j]);
        }

        // Causal mask on the diagonal tile
        if (jt == qt) {
#pragma unroll
            for (int i = 0; i < 4; i++)
#pragma unroll
                for (int j = 0; j < 4; j++)
                    if (tx * 4 + j > ty * 4 + i) s[i][j] = -1e30f;
        }

        // Online softmax update (row stats replicated across the 16 tx lanes)
#pragma unroll
        for (int i = 0; i < 4; i++) {
            float rm = fmaxf(fmaxf(s[i][0], s[i][1]), fmaxf(s[i][2], s[i][3]));
#pragma unroll
            for (int off = 8; off >= 1; off >>= 1)
                rm = fmaxf(rm, __shfl_xor_sync(0xffffffffu, rm, off));
            float mn = fmaxf(m[i], rm);
            float f = __expf(m[i] - mn);
            m[i] = mn;
            float rs = 0.f;
#pragma unroll
            for (int j = 0; j < 4; j++) {
                float p = __expf(s[i][j] - mn);
                s[i][j] = p;
                rs += p;
            }
#pragma unroll
            for (int off = 8; off >= 1; off >>= 1)
                rs += __shfl_xor_sync(0xffffffffu, rs, off);
            l[i] = l[i] * f + rs;
#pragma unroll
            for (int j = 0; j < 4; j++) o[i][j] *= f;
        }

        // Store P transposed: Pts[c][r]
#pragma unroll
        for (int j = 0; j < 4; j++) {
            float4 pv = make_float4(s[0][j], s[1][j], s[2][j], s[3][j]);
            *(float4*)&Pts[(tx * 4 + j) * 64 + ty * 4] = pv;
        }
        __syncthreads();  // all K reads done, P visible

        // Load V tile natural: KVs[c][d]  (overwrites K)
        for (int idx = tid; idx < 1024; idx += 256) {
            int r  = idx >> 4;
            int c4 = (idx & 15) << 2;
            *(float4*)&KVs[r * 64 + c4] =
                *(const float4*)&Vg[(size_t)(kbase + r) * DD + c4];
        }
        __syncthreads();

        // O[i][j] += sum_c P[r_i][c] * V[c][d_j]
#pragma unroll 8
        for (int c = 0; c < 64; c++) {
            float4 p4 = *(float4*)&Pts[c * 64 + ty * 4];
            float4 v4 = *(float4*)&KVs[c * 64 + tx * 4];
            float pv[4] = {p4.x, p4.y, p4.z, p4.w};
            float vv[4] = {v4.x, v4.y, v4.z, v4.w};
#pragma unroll
            for (int i = 0; i < 4; i++)
#pragma unroll
                for (int j = 0; j < 4; j++)
                    o[i][j] = fmaf(pv[i], vv[j], o[i][j]);
        }
    }

    // Normalize and write O
#pragma unroll
    for (int i = 0; i < 4; i++) {
        float inv = 1.0f / l[i];
        float4 ov = make_float4(o[i][0] * inv, o[i][1] * inv, o[i][2] * inv, o[i][3] * inv);
        *(float4*)&Og[(size_t)(qbase + ty * 4 + i) * DD + tx * 4] = ov;
    }
}

// ---------------------------------------------------------------------------
extern "C" void kernel_launch(void* const* d_in, const int* in_sizes, int n_in,
                              void* d_out, int out_size) {
    (void)in_sizes; (void)n_in; (void)out_size;
    const float* x  = (const float*)d_in[0];
    const float* Wq = (const float*)d_in[1];
    const float* Wk = (const float*)d_in[2];
    const float* Wv = (const float*)d_in[3];
    const float* Wo = (const float*)d_in[4];
    float* out = (float*)d_out;

    // QKV projections: 3 GEMMs fused into one launch via blockIdx.z
    qkv_kernel<<<dim3(8, 32, 3), 256>>>(x, Wq, Wk, Wv);

    // Causal flash attention per (q-tile, head, batch)
    flash_kernel<<<dim3(TT / 64, NH, BB), 256>>>();

    // Output projection
    out_kernel<<<dim3(8, 32), 256>>>(Wo, out);
}

// round 2
// speedup vs baseline: 1.3634x; 1.3634x over previous
#include <cuda_runtime.h>
#include <cstdint>

// Problem constants
#define BB 2
#define TT 2048
#define DD 1024
#define NH 16
#define DH 64
#define BT (BB*TT)   // 4096

// Scratch (device globals — no allocation allowed)
__device__ float g_q[BT * DD];
__device__ float g_k[BT * DD];
__device__ float g_v[BT * DD];
__device__ float g_o[BT * DD];

// ---------------------------------------------------------------------------
// TF32 helpers
// ---------------------------------------------------------------------------
__device__ __forceinline__ float to_tf32(float x) {
    unsigned u;
    asm("cvt.rna.tf32.f32 %0, %1;" : "=r"(u) : "f"(x));
    return __uint_as_float(u);
}

__device__ __forceinline__ void mma_tf32(float c[4], const float a[4], const float b[2]) {
    const unsigned* A = reinterpret_cast<const unsigned*>(a);
    const unsigned* B = reinterpret_cast<const unsigned*>(b);
    asm volatile(
        "mma.sync.aligned.m16n8k8.row.col.f32.tf32.tf32.f32 "
        "{%0,%1,%2,%3}, {%4,%5,%6,%7}, {%8,%9}, {%0,%1,%2,%3};\n"
        : "+f"(c[0]), "+f"(c[1]), "+f"(c[2]), "+f"(c[3])
        : "r"(A[0]), "r"(A[1]), "r"(A[2]), "r"(A[3]), "r"(B[0]), "r"(B[1]));
}

// ---------------------------------------------------------------------------
// TF32 tensor-core GEMM: C[4096,1024] = A[4096,1024] @ W[1024,1024]
// Block 128x128x32, 256 threads = 8 warps (2 M x 4 N), warp tile 64x32,
// mma m16n8k8 (4 m-tiles x 4 n-tiles per warp per k-step).
// ---------------------------------------------------------------------------
#define GM 128
#define GN 128
#define GK 32
#define GPAD 4

__device__ __forceinline__ void gemm_tf32(const float* __restrict__ A,
                                          const float* __restrict__ W,
                                          float* __restrict__ C) {
    constexpr int N = 1024, K = 1024;
    __shared__ float As[GK][GM + GPAD];  // A tile, k-major: As[k][m]
    __shared__ float Bs[GK][GN + GPAD];  // B tile, k-major: Bs[k][n]

    const int tid  = threadIdx.x;
    const int lane = tid & 31;
    const int warp = tid >> 5;
    const int warp_m = warp & 1;         // 0..1  -> 64-row slice
    const int warp_n = warp >> 1;        // 0..3  -> 32-col slice
    const int rb = blockIdx.y * GM;
    const int cb = blockIdx.x * GN;

    const int lq = lane >> 2;            // 0..7
    const int lr = lane & 3;             // 0..3

    float acc[4][4][4];                  // [mt][nt][reg]
#pragma unroll
    for (int i = 0; i < 4; i++)
#pragma unroll
        for (int j = 0; j < 4; j++)
#pragma unroll
            for (int r = 0; r < 4; r++) acc[i][j][r] = 0.f;

    for (int k0 = 0; k0 < K; k0 += GK) {
        // Load A tile (128 x 32), store transposed k-major with tf32 rounding.
#pragma unroll
        for (int it = 0; it < 4; it++) {
            int idx = tid + it * 256;        // float4 units, 0..1023
            int r  = idx & 127;
            int cq = idx >> 7;               // 0..7
            float4 v = *(const float4*)&A[(size_t)(rb + r) * K + k0 + cq * 4];
            As[cq * 4 + 0][r] = to_tf32(v.x);
            As[cq * 4 + 1][r] = to_tf32(v.y);
            As[cq * 4 + 2][r] = to_tf32(v.z);
            As[cq * 4 + 3][r] = to_tf32(v.w);
        }
        // Load B tile (32 x 128), natural layout.
#pragma unroll
        for (int it = 0; it < 4; it++) {
            int idx = tid + it * 256;
            int r  = idx >> 5;               // 0..31
            int c4 = (idx & 31) << 2;        // 0..124
            float4 v = *(const float4*)&W[(size_t)(k0 + r) * N + cb + c4];
            float4 t;
            t.x = to_tf32(v.x); t.y = to_tf32(v.y);
            t.z = to_tf32(v.z); t.w = to_tf32(v.w);
            *(float4*)&Bs[r][c4] = t;
        }
        __syncthreads();

#pragma unroll
        for (int ks = 0; ks < 4; ks++) {
            const int k = ks * 8;
            float af[4][4];
#pragma unroll
            for (int mt = 0; mt < 4; mt++) {
                int m = warp_m * 64 + mt * 16;
                af[mt][0] = As[k + lr    ][m + lq    ];
                af[mt][1] = As[k + lr    ][m + lq + 8];
                af[mt][2] = As[k + lr + 4][m + lq    ];
                af[mt][3] = As[k + lr + 4][m + lq + 8];
            }
            float bf[4][2];
#pragma unroll
            for (int nt = 0; nt < 4; nt++) {
                int n = warp_n * 32 + nt * 8;
                bf[nt][0] = Bs[k + lr    ][n + lq];
                bf[nt][1] = Bs[k + lr + 4][n + lq];
            }
#pragma unroll
            for (int mt = 0; mt < 4; mt++)
#pragma unroll
                for (int nt = 0; nt < 4; nt++)
                    mma_tf32(acc[mt][nt], af[mt], bf[nt]);
        }
        __syncthreads();
    }

    // Epilogue: c0,c1 at (row=lq, col=2*lr,+1); c2,c3 at row+8.
#pragma unroll
    for (int mt = 0; mt < 4; mt++) {
        int r0 = rb + warp_m * 64 + mt * 16 + lq;
#pragma unroll
        for (int nt = 0; nt < 4; nt++) {
            int c = cb + warp_n * 32 + nt * 8 + 2 * lr;
            *(float2*)&C[(size_t)r0 * N + c] =
                make_float2(acc[mt][nt][0], acc[mt][nt][1]);
            *(float2*)&C[(size_t)(r0 + 8) * N + c] =
                make_float2(acc[mt][nt][2], acc[mt][nt][3]);
        }
    }
}

__global__ __launch_bounds__(256, 2) void qkv_kernel(const float* __restrict__ X,
                                                     const float* __restrict__ Wq,
                                                     const float* __restrict__ Wk,
                                                     const float* __restrict__ Wv) {
    const float* W = (blockIdx.z == 0) ? Wq : ((blockIdx.z == 1) ? Wk : Wv);
    float* C = (blockIdx.z == 0) ? g_q : ((blockIdx.z == 1) ? g_k : g_v);
    gemm_tf32(X, W, C);
}

__global__ __launch_bounds__(256, 2) void out_kernel(const float* __restrict__ Wo,
                                                     float* __restrict__ out) {
    gemm_tf32(g_o, Wo, out);
}

// ---------------------------------------------------------------------------
// Flash attention (causal), fp32 (unchanged from R1 — tensorized next round).
// ---------------------------------------------------------------------------
__global__ __launch_bounds__(256) void flash_kernel() {
    __shared__ float Qts[64 * 64];
    __shared__ float KVs[64 * 64];
    __shared__ float Pts[64 * 64];

    const int tid = threadIdx.x;
    const int tx = tid & 15;
    const int ty = tid >> 4;
    const int qt = blockIdx.x;
    const int h  = blockIdx.y;
    const int b  = blockIdx.z;
    const int qbase = qt * 64;
    const float scale = 0.125f;

    const size_t headOff = (size_t)b * TT * DD + (size_t)h * DH;
    const float* Qg = g_q + headOff;
    const float* Kg = g_k + headOff;
    const float* Vg = g_v + headOff;
    float* Og = g_o + headOff;

    for (int idx = tid; idx < 1024; idx += 256) {
        int r  = idx >> 4;
        int c4 = (idx & 15) << 2;
        float4 v = *(const float4*)&Qg[(size_t)(qbase + r) * DD + c4];
        Qts[(c4 + 0) * 64 + r] = v.x * scale;
        Qts[(c4 + 1) * 64 + r] = v.y * scale;
        Qts[(c4 + 2) * 64 + r] = v.z * scale;
        Qts[(c4 + 3) * 64 + r] = v.w * scale;
    }

    float m[4], l[4], o[4][4];
#pragma unroll
    for (int i = 0; i < 4; i++) {
        m[i] = -1e30f;
        l[i] = 0.f;
#pragma unroll
        for (int j = 0; j < 4; j++) o[i][j] = 0.f;
    }

    for (int jt = 0; jt <= qt; jt++) {
        const int kbase = jt * 64;

        __syncthreads();

        for (int idx = tid; idx < 1024; idx += 256) {
            int r  = idx >> 4;
            int c4 = (idx & 15) << 2;
            float4 v = *(const float4*)&Kg[(size_t)(kbase + r) * DD + c4];
            KVs[(c4 + 0) * 64 + r] = v.x;
            KVs[(c4 + 1) * 64 + r] = v.y;
            KVs[(c4 + 2) * 64 + r] = v.z;
            KVs[(c4 + 3) * 64 + r] = v.w;
        }
        __syncthreads();

        float s[4][4];
#pragma unroll
        for (int i = 0; i < 4; i++)
#pragma unroll
            for (int j = 0; j < 4; j++) s[i][j] = 0.f;

#pragma unroll 8
        for (int d = 0; d < 64; d++) {
            float4 a4 = *(float4*)&Qts[d * 64 + ty * 4];
            float4 b4 = *(float4*)&KVs[d * 64 + tx * 4];
            float av[4] = {a4.x, a4.y, a4.z, a4.w};
            float bv[4] = {b4.x, b4.y, b4.z, b4.w};
#pragma unroll
            for (int i = 0; i < 4; i++)
#pragma unroll
                for (int j = 0; j < 4; j++)
                    s[i][j] = fmaf(av[i], bv[j], s[i][j]);
        }

        if (jt == qt) {
#pragma unroll
            for (int i = 0; i < 4; i++)
#pragma unroll
                for (int j = 0; j < 4; j++)
                    if (tx * 4 + j > ty * 4 + i) s[i][j] = -1e30f;
        }

#pragma unroll
        for (int i = 0; i < 4; i++) {
            float rm = fmaxf(fmaxf(s[i][0], s[i][1]), fmaxf(s[i][2], s[i][3]));
#pragma unroll
            for (int off = 8; off >= 1; off >>= 1)
                rm = fmaxf(rm, __shfl_xor_sync(0xffffffffu, rm, off));
            float mn = fmaxf(m[i], rm);
            float f = __expf(m[i] - mn);
            m[i] = mn;
            float rs = 0.f;
#pragma unroll
            for (int j = 0; j < 4; j++) {
                float p = __expf(s[i][j] - mn);
                s[i][j] = p;
                rs += p;
            }
#pragma unroll
            for (int off = 8; off >= 1; off >>= 1)
                rs += __shfl_xor_sync(0xffffffffu, rs, off);
            l[i] = l[i] * f + rs;
#pragma unroll
            for (int j = 0; j < 4; j++) o[i][j] *= f;
        }

#pragma unroll
        for (int j = 0; j < 4; j++) {
            float4 pv = make_float4(s[0][j], s[1][j], s[2][j], s[3][j]);
            *(float4*)&Pts[(tx * 4 + j) * 64 + ty * 4] = pv;
        }
        __syncthreads();

        for (int idx = tid; idx < 1024; idx += 256) {
            int r  = idx >> 4;
            int c4 = (idx & 15) << 2;
            *(float4*)&KVs[r * 64 + c4] =
                *(const float4*)&Vg[(size_t)(kbase + r) * DD + c4];
        }
        __syncthreads();

#pragma unroll 8
        for (int c = 0; c < 64; c++) {
            float4 p4 = *(float4*)&Pts[c * 64 + ty * 4];
            float4 v4 = *(float4*)&KVs[c * 64 + tx * 4];
            float pv[4] = {p4.x, p4.y, p4.z, p4.w};
            float vv[4] = {v4.x, v4.y, v4.z, v4.w};
#pragma unroll
            for (int i = 0; i < 4; i++)
#pragma unroll
                for (int j = 0; j < 4; j++)
                    o[i][j] = fmaf(pv[i], vv[j], o[i][j]);
        }
    }

#pragma unroll
    for (int i = 0; i < 4; i++) {
        float inv = 1.0f / l[i];
        float4 ov = make_float4(o[i][0] * inv, o[i][1] * inv, o[i][2] * inv, o[i][3] * inv);
        *(float4*)&Og[(size_t)(qbase + ty * 4 + i) * DD + tx * 4] = ov;
    }
}

// ---------------------------------------------------------------------------
extern "C" void kernel_launch(void* const* d_in, const int* in_sizes, int n_in,
                              void* d_out, int out_size) {
    (void)in_sizes; (void)n_in; (void)out_size;
    const float* x  = (const float*)d_in[0];
    const float* Wq = (const float*)d_in[1];
    const float* Wk = (const float*)d_in[2];
    const float* Wv = (const float*)d_in[3];
    const float* Wo = (const float*)d_in[4];
    float* out = (float*)d_out;

    qkv_kernel<<<dim3(8, 32, 3), 256>>>(x, Wq, Wk, Wv);
    flash_kernel<<<dim3(TT / 64, NH, BB), 256>>>();
    out_kernel<<<dim3(8, 32), 256>>>(Wo, out);
}

// round 3
// speedup vs baseline: 2.5605x; 1.8780x over previous
#include <cuda_runtime.h>
#include <cstdint>

// Problem constants
#define BB 2
#define TT 2048
#define DD 1024
#define NH 16
#define DH 64
#define BT (BB*TT)   // 4096

// Scratch (device globals — no allocation allowed)
__device__ float g_q[BT * DD];
__device__ float g_k[BT * DD];
__device__ float g_v[BT * DD];
__device__ float g_o[BT * DD];

// ---------------------------------------------------------------------------
// TF32 helpers
// ---------------------------------------------------------------------------
__device__ __forceinline__ float to_tf32(float x) {
    unsigned u;
    asm("cvt.rna.tf32.f32 %0, %1;" : "=r"(u) : "f"(x));
    return __uint_as_float(u);
}

__device__ __forceinline__ void mma_tf32(float c[4], const float a[4], const float b[2]) {
    const unsigned* A = reinterpret_cast<const unsigned*>(a);
    const unsigned* B = reinterpret_cast<const unsigned*>(b);
    asm volatile(
        "mma.sync.aligned.m16n8k8.row.col.f32.tf32.tf32.f32 "
        "{%0,%1,%2,%3}, {%4,%5,%6,%7}, {%8,%9}, {%0,%1,%2,%3};\n"
        : "+f"(c[0]), "+f"(c[1]), "+f"(c[2]), "+f"(c[3])
        : "r"(A[0]), "r"(A[1]), "r"(A[2]), "r"(A[3]), "r"(B[0]), "r"(B[1]));
}

// ---------------------------------------------------------------------------
// TF32 tensor-core GEMM: C[4096,1024] = A[4096,1024] @ W[1024,1024]
// (unchanged from R2 — validated fragment layouts)
// ---------------------------------------------------------------------------
#define GM 128
#define GN 128
#define GK 32
#define GPAD 4

__device__ __forceinline__ void gemm_tf32(const float* __restrict__ A,
                                          const float* __restrict__ W,
                                          float* __restrict__ C) {
    constexpr int N = 1024, K = 1024;
    __shared__ float As[GK][GM + GPAD];  // k-major: As[k][m]
    __shared__ float Bs[GK][GN + GPAD];  // k-major: Bs[k][n]

    const int tid  = threadIdx.x;
    const int lane = tid & 31;
    const int warp = tid >> 5;
    const int warp_m = warp & 1;
    const int warp_n = warp >> 1;
    const int rb = blockIdx.y * GM;
    const int cb = blockIdx.x * GN;
    const int lq = lane >> 2;
    const int lr = lane & 3;

    float acc[4][4][4];
#pragma unroll
    for (int i = 0; i < 4; i++)
#pragma unroll
        for (int j = 0; j < 4; j++)
#pragma unroll
            for (int r = 0; r < 4; r++) acc[i][j][r] = 0.f;

    for (int k0 = 0; k0 < K; k0 += GK) {
#pragma unroll
        for (int it = 0; it < 4; it++) {
            int idx = tid + it * 256;
            int r  = idx & 127;
            int cq = idx >> 7;
            float4 v = *(const float4*)&A[(size_t)(rb + r) * K + k0 + cq * 4];
            As[cq * 4 + 0][r] = to_tf32(v.x);
            As[cq * 4 + 1][r] = to_tf32(v.y);
            As[cq * 4 + 2][r] = to_tf32(v.z);
            As[cq * 4 + 3][r] = to_tf32(v.w);
        }
#pragma unroll
        for (int it = 0; it < 4; it++) {
            int idx = tid + it * 256;
            int r  = idx >> 5;
            int c4 = (idx & 31) << 2;
            float4 v = *(const float4*)&W[(size_t)(k0 + r) * N + cb + c4];
            float4 t;
            t.x = to_tf32(v.x); t.y = to_tf32(v.y);
            t.z = to_tf32(v.z); t.w = to_tf32(v.w);
            *(float4*)&Bs[r][c4] = t;
        }
        __syncthreads();

#pragma unroll
        for (int ks = 0; ks < 4; ks++) {
            const int k = ks * 8;
            float af[4][4];
#pragma unroll
            for (int mt = 0; mt < 4; mt++) {
                int m = warp_m * 64 + mt * 16;
                af[mt][0] = As[k + lr    ][m + lq    ];
                af[mt][1] = As[k + lr    ][m + lq + 8];
                af[mt][2] = As[k + lr + 4][m + lq    ];
                af[mt][3] = As[k + lr + 4][m + lq + 8];
            }
            float bf[4][2];
#pragma unroll
            for (int nt = 0; nt < 4; nt++) {
                int n = warp_n * 32 + nt * 8;
                bf[nt][0] = Bs[k + lr    ][n + lq];
                bf[nt][1] = Bs[k + lr + 4][n + lq];
            }
#pragma unroll
            for (int mt = 0; mt < 4; mt++)
#pragma unroll
                for (int nt = 0; nt < 4; nt++)
                    mma_tf32(acc[mt][nt], af[mt], bf[nt]);
        }
        __syncthreads();
    }

#pragma unroll
    for (int mt = 0; mt < 4; mt++) {
        int r0 = rb + warp_m * 64 + mt * 16 + lq;
#pragma unroll
        for (int nt = 0; nt < 4; nt++) {
            int c = cb + warp_n * 32 + nt * 8 + 2 * lr;
            *(float2*)&C[(size_t)r0 * N + c] =
                make_float2(acc[mt][nt][0], acc[mt][nt][1]);
            *(float2*)&C[(size_t)(r0 + 8) * N + c] =
                make_float2(acc[mt][nt][2], acc[mt][nt][3]);
        }
    }
}

__global__ __launch_bounds__(256, 2) void qkv_kernel(const float* __restrict__ X,
                                                     const float* __restrict__ Wq,
                                                     const float* __restrict__ Wk,
                                                     const float* __restrict__ Wv) {
    const float* W = (blockIdx.z == 0) ? Wq : ((blockIdx.z == 1) ? Wk : Wv);
    float* C = (blockIdx.z == 0) ? g_q : ((blockIdx.z == 1) ? g_k : g_v);
    gemm_tf32(X, W, C);
}

__global__ __launch_bounds__(256, 2) void out_kernel(const float* __restrict__ Wo,
                                                     float* __restrict__ out) {
    gemm_tf32(g_o, Wo, out);
}

// ---------------------------------------------------------------------------
// Tensor-core flash attention (causal), TF32 mma with fp32 accumulate.
// Block = 128 q rows for one (b,h). 8 warps, each owns m16 slice.
// K stored natural [kv][d] stride 68 (B-frag reads bank-conflict-free),
// V stored natural [kv][d] stride 72 (B-frag reads bank-conflict-free).
// P converted C-frag -> A-frag via intra-quad shuffles (no smem bounce).
// ---------------------------------------------------------------------------
#define KS_STRIDE 68
#define VS_STRIDE 72

__global__ __launch_bounds__(256) void flash_kernel() {
    __shared__ float Ks[64][KS_STRIDE];   // K tile (also Q staging)
    __shared__ float Vs[64][VS_STRIDE];   // V tile

    const int tid  = threadIdx.x;
    const int lane = tid & 31;
    const int w    = tid >> 5;          // warp 0..7 -> q rows w*16..w*16+15
    const int lq   = lane >> 2;         // 0..7
    const int lr   = lane & 3;          // 0..3
    const unsigned FULL = 0xffffffffu;

    const int qt = (int)gridDim.x - 1 - (int)blockIdx.x;  // heavy blocks first
    const int h  = blockIdx.y;
    const int b  = blockIdx.z;
    const int qbase = qt * 128;

    const size_t base = (size_t)b * TT * DD + (size_t)h * DH;
    const float* Qg = g_q + base;
    const float* Kg = g_k + base;
    const float* Vg = g_v + base;
    float* Og = g_o + base;

    // ---- Stage Q (pre-scaled, tf32-rounded) through Ks; build A-frags in regs
    float qa[8][4];
    const int halfw = w >> 2;
    const int lrow  = (w & 3) * 16;
#pragma unroll
    for (int hf = 0; hf < 2; hf++) {
#pragma unroll
        for (int it = 0; it < 4; it++) {
            int idx = tid + it * 256;      // 1024 float4 units
            int r  = idx >> 4;             // 0..63
            int c4 = (idx & 15) << 2;      // 0..60
            float4 v = *(const float4*)&Qg[(size_t)(qbase + hf * 64 + r) * DD + c4];
            Ks[r][c4 + 0] = to_tf32(v.x * 0.125f);
            Ks[r][c4 + 1] = to_tf32(v.y * 0.125f);
            Ks[r][c4 + 2] = to_tf32(v.z * 0.125f);
            Ks[r][c4 + 3] = to_tf32(v.w * 0.125f);
        }
        __syncthreads();
        if (halfw == hf) {
#pragma unroll
            for (int kc = 0; kc < 8; kc++) {
                qa[kc][0] = Ks[lrow + lq    ][kc * 8 + lr    ];
                qa[kc][1] = Ks[lrow + lq + 8][kc * 8 + lr    ];
                qa[kc][2] = Ks[lrow + lq    ][kc * 8 + lr + 4];
                qa[kc][3] = Ks[lrow + lq + 8][kc * 8 + lr + 4];
            }
        }
        __syncthreads();
    }

    // Online softmax state (rows lq and lq+8 of this warp's m16 slice)
    float m0 = -1e30f, m1 = -1e30f, l0 = 0.f, l1 = 0.f;
    float oacc[8][4];
#pragma unroll
    for (int dt = 0; dt < 8; dt++)
#pragma unroll
        for (int r = 0; r < 4; r++) oacc[dt][r] = 0.f;

    const int qrow0 = qbase + w * 16 + lq;   // global q row of c0/c1
    const int jmax = 2 * qt + 1;

    for (int jt = 0; jt <= jmax; jt++) {
        const int kv0 = jt * 64;

        __syncthreads();   // previous iteration's Ks/Vs reads complete
        // ---- Load K, V tiles (coalesced float4, tf32-rounded)
#pragma unroll
        for (int it = 0; it < 4; it++) {
            int idx = tid + it * 256;
            int r  = idx >> 4;
            int c4 = (idx & 15) << 2;
            float4 kv4 = *(const float4*)&Kg[(size_t)(kv0 + r) * DD + c4];
            Ks[r][c4 + 0] = to_tf32(kv4.x);
            Ks[r][c4 + 1] = to_tf32(kv4.y);
            Ks[r][c4 + 2] = to_tf32(kv4.z);
            Ks[r][c4 + 3] = to_tf32(kv4.w);
            float4 vv4 = *(const float4*)&Vg[(size_t)(kv0 + r) * DD + c4];
            Vs[r][c4 + 0] = to_tf32(vv4.x);
            Vs[r][c4 + 1] = to_tf32(vv4.y);
            Vs[r][c4 + 2] = to_tf32(vv4.z);
            Vs[r][c4 + 3] = to_tf32(vv4.w);
        }
        __syncthreads();

        // ---- S = Q K^T  (B-frag reads K natural layout, conflict-free)
        float sa[8][4];
#pragma unroll
        for (int nt = 0; nt < 8; nt++)
#pragma unroll
            for (int r = 0; r < 4; r++) sa[nt][r] = 0.f;

#pragma unroll
        for (int kc = 0; kc < 8; kc++) {
#pragma unroll
            for (int nt = 0; nt < 8; nt++) {
                float bv[2];
                bv[0] = Ks[nt * 8 + lq][kc * 8 + lr    ];
                bv[1] = Ks[nt * 8 + lq][kc * 8 + lr + 4];
                mma_tf32(sa[nt], qa[kc], bv);
            }
        }

        // ---- Causal mask (only tiles that touch the diagonal)
        if (jt >= 2 * qt) {
#pragma unroll
            for (int nt = 0; nt < 8; nt++) {
                int kc0 = kv0 + nt * 8 + 2 * lr;
                if (kc0     > qrow0)     sa[nt][0] = -1e30f;
                if (kc0 + 1 > qrow0)     sa[nt][1] = -1e30f;
                if (kc0     > qrow0 + 8) sa[nt][2] = -1e30f;
                if (kc0 + 1 > qrow0 + 8) sa[nt][3] = -1e30f;
            }
        }

        // ---- Online softmax on fragments
        float mx0 = -1e30f, mx1 = -1e30f;
#pragma unroll
        for (int nt = 0; nt < 8; nt++) {
            mx0 = fmaxf(mx0, fmaxf(sa[nt][0], sa[nt][1]));
            mx1 = fmaxf(mx1, fmaxf(sa[nt][2], sa[nt][3]));
        }
        mx0 = fmaxf(mx0, __shfl_xor_sync(FULL, mx0, 1));
        mx0 = fmaxf(mx0, __shfl_xor_sync(FULL, mx0, 2));
        mx1 = fmaxf(mx1, __shfl_xor_sync(FULL, mx1, 1));
        mx1 = fmaxf(mx1, __shfl_xor_sync(FULL, mx1, 2));

        float nm0 = fmaxf(m0, mx0), nm1 = fmaxf(m1, mx1);
        float f0 = __expf(m0 - nm0), f1 = __expf(m1 - nm1);
        m0 = nm0; m1 = nm1;

        float s0 = 0.f, s1 = 0.f;
#pragma unroll
        for (int nt = 0; nt < 8; nt++) {
            float p0 = __expf(sa[nt][0] - nm0);
            float p1 = __expf(sa[nt][1] - nm0);
            float p2 = __expf(sa[nt][2] - nm1);
            float p3 = __expf(sa[nt][3] - nm1);
            s0 += p0 + p1;
            s1 += p2 + p3;
            sa[nt][0] = to_tf32(p0);
            sa[nt][1] = to_tf32(p1);
            sa[nt][2] = to_tf32(p2);
            sa[nt][3] = to_tf32(p3);
        }
        s0 += __shfl_xor_sync(FULL, s0, 1);
        s0 += __shfl_xor_sync(FULL, s0, 2);
        s1 += __shfl_xor_sync(FULL, s1, 1);
        s1 += __shfl_xor_sync(FULL, s1, 2);
        l0 = l0 * f0 + s0;
        l1 = l1 * f1 + s1;

#pragma unroll
        for (int dt = 0; dt < 8; dt++) {
            oacc[dt][0] *= f0;
            oacc[dt][1] *= f0;
            oacc[dt][2] *= f1;
            oacc[dt][3] *= f1;
        }

        // ---- O += P V : P C-frag -> A-frag via intra-quad shuffles
        const int src0 = (lq << 2) | (lr >> 1);
        const int src1 = src0 + 2;
        const bool odd = (lr & 1);
#pragma unroll
        for (int kc = 0; kc < 8; kc++) {
            float t00 = __shfl_sync(FULL, sa[kc][0], src0);
            float t01 = __shfl_sync(FULL, sa[kc][1], src0);
            float t10 = __shfl_sync(FULL, sa[kc][2], src0);
            float t11 = __shfl_sync(FULL, sa[kc][3], src0);
            float u00 = __shfl_sync(FULL, sa[kc][0], src1);
            float u01 = __shfl_sync(FULL, sa[kc][1], src1);
            float u10 = __shfl_sync(FULL, sa[kc][2], src1);
            float u11 = __shfl_sync(FULL, sa[kc][3], src1);
            float pa[4];
            pa[0] = odd ? t01 : t00;
            pa[1] = odd ? t11 : t10;
            pa[2] = odd ? u01 : u00;
            pa[3] = odd ? u11 : u10;
#pragma unroll
            for (int dt = 0; dt < 8; dt++) {
                float bv[2];
                bv[0] = Vs[kc * 8 + lr    ][dt * 8 + lq];
                bv[1] = Vs[kc * 8 + lr + 4][dt * 8 + lq];
                mma_tf32(oacc[dt], pa, bv);
            }
        }
    }

    // ---- Epilogue: normalize, write O
    const float inv0 = 1.0f / l0;
    const float inv1 = 1.0f / l1;
#pragma unroll
    for (int dt = 0; dt < 8; dt++) {
        int c = dt * 8 + 2 * lr;
        *(float2*)&Og[(size_t)qrow0 * DD + c] =
            make_float2(oacc[dt][0] * inv0, oacc[dt][1] * inv0);
        *(float2*)&Og[(size_t)(qrow0 + 8) * DD + c] =
            make_float2(oacc[dt][2] * inv1, oacc[dt][3] * inv1);
    }
}

// ---------------------------------------------------------------------------
extern "C" void kernel_launch(void* const* d_in, const int* in_sizes, int n_in,
                              void* d_out, int out_size) {
    (void)in_sizes; (void)n_in; (void)out_size;
    const float* x  = (const float*)d_in[0];
    const float* Wq = (const float*)d_in[1];
    const float* Wk = (const float*)d_in[2];
    const float* Wv = (const float*)d_in[3];
    const float* Wo = (const float*)d_in[4];
    float* out = (float*)d_out;

    qkv_kernel<<<dim3(8, 32, 3), 256>>>(x, Wq, Wk, Wv);
    flash_kernel<<<dim3(TT / 128, NH, BB), 256>>>();
    out_kernel<<<dim3(8, 32), 256>>>(Wo, out);
}

// round 4
// speedup vs baseline: 3.4026x; 1.3289x over previous
#include <cuda_runtime.h>
#include <cstdint>

// Problem constants
#define BB 2
#define TT 2048
#define DD 1024
#define NH 16
#define DH 64
#define BT (BB*TT)   // 4096

// Scratch (device globals — no allocation allowed)
__device__ float g_q[BT * DD];
__device__ float g_k[BT * DD];
__device__ float g_v[BT * DD];
__device__ float g_o[BT * DD];

// ---------------------------------------------------------------------------
// TF32 helpers
// ---------------------------------------------------------------------------
__device__ __forceinline__ float to_tf32(float x) {
    unsigned u;
    asm("cvt.rna.tf32.f32 %0, %1;" : "=r"(u) : "f"(x));
    return __uint_as_float(u);
}

__device__ __forceinline__ void mma_tf32(float c[4], const float a[4], const float b[2]) {
    const unsigned* A = reinterpret_cast<const unsigned*>(a);
    const unsigned* B = reinterpret_cast<const unsigned*>(b);
    asm volatile(
        "mma.sync.aligned.m16n8k8.row.col.f32.tf32.tf32.f32 "
        "{%0,%1,%2,%3}, {%4,%5,%6,%7}, {%8,%9}, {%0,%1,%2,%3};\n"
        : "+f"(c[0]), "+f"(c[1]), "+f"(c[2]), "+f"(c[3])
        : "r"(A[0]), "r"(A[1]), "r"(A[2]), "r"(A[3]), "r"(B[0]), "r"(B[1]));
}

__device__ __forceinline__ void mma_tf32_u(float c[4], const unsigned a[4], const float b[2]) {
    const unsigned* B = reinterpret_cast<const unsigned*>(b);
    asm volatile(
        "mma.sync.aligned.m16n8k8.row.col.f32.tf32.tf32.f32 "
        "{%0,%1,%2,%3}, {%4,%5,%6,%7}, {%8,%9}, {%0,%1,%2,%3};\n"
        : "+f"(c[0]), "+f"(c[1]), "+f"(c[2]), "+f"(c[3])
        : "r"(a[0]), "r"(a[1]), "r"(a[2]), "r"(a[3]), "r"(B[0]), "r"(B[1]));
}

// ldmatrix x4: lane L supplies row address; regs r0..r3 <- matrices from
// lanes 0-7, 8-15, 16-23, 24-31. On tf32 data (2 b16 = 1 tf32), each reg is
// the tf32 element at (row L/4, col L%4) of its 8x4-tf32 matrix.
__device__ __forceinline__ void ldsm4(unsigned r[4], const void* p) {
    unsigned a = (unsigned)__cvta_generic_to_shared(p);
    asm volatile("ldmatrix.sync.aligned.m8n8.x4.shared.b16 {%0,%1,%2,%3}, [%4];"
                 : "=r"(r[0]), "=r"(r[1]), "=r"(r[2]), "=r"(r[3]) : "r"(a));
}

// ---------------------------------------------------------------------------
// TF32 tensor-core GEMM v3: C[4096,1024] = A[4096,1024] @ W[1024,1024]
// 128x128 block, GK=16, double-buffered smem, ldmatrix A-fragments,
// register-prefetch of next tile, one barrier per k-iter.
// A smem layout: row-major [128][16] with XOR swizzle on 16B units:
//   phys_unit = u ^ ((row>>1) & 3)   (conflict-free STS.128 and LDSM)
// ---------------------------------------------------------------------------
#define GM 128
#define GN 128
#define GK 16

__device__ __forceinline__ void gemm_tf32(const float* __restrict__ A,
                                          const float* __restrict__ W,
                                          float* __restrict__ C) {
    constexpr int N = 1024, K = 1024;
    __shared__ float As[2][GM * GK];       // swizzled, 8KB per stage
    __shared__ float Bs[2][GK][GN + 4];    // natural [k][n], 8.25KB per stage

    const int tid  = threadIdx.x;
    const int lane = tid & 31;
    const int warp = tid >> 5;
    const int warp_m = warp & 1;
    const int warp_n = warp >> 1;
    const int rb = blockIdx.y * GM;
    const int cb = blockIdx.x * GN;
    const int lq = lane >> 2;
    const int lr = lane & 3;

    // per-thread global-load coordinates
    const int ar = tid >> 2;            // A row (0..63; +64 on second half)
    const int au = tid & 3;             // A 16B unit within row
    const int bk = tid >> 5;            // B k-row (0..7; +8 on second half)
    const int bc = (tid & 31) << 2;     // B col

    float acc[4][4][4];
#pragma unroll
    for (int i = 0; i < 4; i++)
#pragma unroll
        for (int j = 0; j < 4; j++)
#pragma unroll
            for (int r = 0; r < 4; r++) acc[i][j][r] = 0.f;

    // ---- Prologue: stage tile 0
#pragma unroll
    for (int h = 0; h < 2; h++) {
        int r = ar + h * 64;
        float4 v = *(const float4*)&A[(size_t)(rb + r) * K + au * 4];
        float4 t;
        t.x = to_tf32(v.x); t.y = to_tf32(v.y);
        t.z = to_tf32(v.z); t.w = to_tf32(v.w);
        *(float4*)&As[0][r * GK + ((au ^ ((r >> 1) & 3)) << 2)] = t;

        int kr = bk + h * 8;
        float4 wv = *(const float4*)&W[(size_t)kr * N + cb + bc];
        float4 u;
        u.x = to_tf32(wv.x); u.y = to_tf32(wv.y);
        u.z = to_tf32(wv.z); u.w = to_tf32(wv.w);
        *(float4*)&Bs[0][kr][bc] = u;
    }
    __syncthreads();

    const int mrow = warp_m * 64;
    const int nb   = warp_n * 32;
    const int lrow = lane & 15;          // ldmatrix row within m16
    const int lsel = lane >> 4;          // ldmatrix k-half select

    for (int it = 0; it < K / GK; ++it) {
        const int buf = it & 1;

        // ---- Prefetch next tile into registers (overlaps with compute)
        float4 pa[2], pb[2];
        const bool more = (it < K / GK - 1);
        if (more) {
            const int k0 = (it + 1) * GK;
#pragma unroll
            for (int h = 0; h < 2; h++) {
                pa[h] = *(const float4*)&A[(size_t)(rb + ar + h * 64) * K + k0 + au * 4];
                pb[h] = *(const float4*)&W[(size_t)(k0 + bk + h * 8) * N + cb + bc];
            }
        }

        // ---- Compute on current buffer
#pragma unroll
        for (int kc = 0; kc < 2; kc++) {
            unsigned af[4][4];
#pragma unroll
            for (int mt = 0; mt < 4; mt++) {
                int row  = mrow + mt * 16 + lrow;
                int unit = (kc * 2 + lsel) ^ ((row >> 1) & 3);
                ldsm4(af[mt], &As[buf][row * GK + unit * 4]);
            }
            float bf[4][2];
#pragma unroll
            for (int nt = 0; nt < 4; nt++) {
                bf[nt][0] = Bs[buf][kc * 8 + lr    ][nb + nt * 8 + lq];
                bf[nt][1] = Bs[buf][kc * 8 + lr + 4][nb + nt * 8 + lq];
            }
#pragma unroll
            for (int mt = 0; mt < 4; mt++)
#pragma unroll
                for (int nt = 0; nt < 4; nt++)
                    mma_tf32_u(acc[mt][nt], af[mt], bf[nt]);
        }

        // ---- Convert + store prefetched tile into the other buffer
        if (more) {
#pragma unroll
            for (int h = 0; h < 2; h++) {
                int r = ar + h * 64;
                float4 t;
                t.x = to_tf32(pa[h].x); t.y = to_tf32(pa[h].y);
                t.z = to_tf32(pa[h].z); t.w = to_tf32(pa[h].w);
                *(float4*)&As[buf ^ 1][r * GK + ((au ^ ((r >> 1) & 3)) << 2)] = t;
                float4 u;
                u.x = to_tf32(pb[h].x); u.y = to_tf32(pb[h].y);
                u.z = to_tf32(pb[h].z); u.w = to_tf32(pb[h].w);
                *(float4*)&Bs[buf ^ 1][bk + h * 8][bc] = u;
            }
        }
        __syncthreads();
    }

    // ---- Epilogue
#pragma unroll
    for (int mt = 0; mt < 4; mt++) {
        int r0 = rb + warp_m * 64 + mt * 16 + lq;
#pragma unroll
        for (int nt = 0; nt < 4; nt++) {
            int c = cb + warp_n * 32 + nt * 8 + 2 * lr;
            *(float2*)&C[(size_t)r0 * N + c] =
                make_float2(acc[mt][nt][0], acc[mt][nt][1]);
            *(float2*)&C[(size_t)(r0 + 8) * N + c] =
                make_float2(acc[mt][nt][2], acc[mt][nt][3]);
        }
    }
}

__global__ __launch_bounds__(256, 2) void qkv_kernel(const float* __restrict__ X,
                                                     const float* __restrict__ Wq,
                                                     const float* __restrict__ Wk,
                                                     const float* __restrict__ Wv) {
    const float* W = (blockIdx.z == 0) ? Wq : ((blockIdx.z == 1) ? Wk : Wv);
    float* C = (blockIdx.z == 0) ? g_q : ((blockIdx.z == 1) ? g_k : g_v);
    gemm_tf32(X, W, C);
}

__global__ __launch_bounds__(256, 2) void out_kernel(const float* __restrict__ Wo,
                                                     float* __restrict__ out) {
    gemm_tf32(g_o, Wo, out);
}

// ---------------------------------------------------------------------------
// Tensor-core flash attention (causal), TF32 mma with fp32 accumulate.
// (unchanged from R3 — validated at rel_err 5.1e-4)
// ---------------------------------------------------------------------------
#define KS_STRIDE 68
#define VS_STRIDE 72

__global__ __launch_bounds__(256) void flash_kernel() {
    __shared__ float Ks[64][KS_STRIDE];
    __shared__ float Vs[64][VS_STRIDE];

    const int tid  = threadIdx.x;
    const int lane = tid & 31;
    const int w    = tid >> 5;
    const int lq   = lane >> 2;
    const int lr   = lane & 3;
    const unsigned FULL = 0xffffffffu;

    const int qt = (int)gridDim.x - 1 - (int)blockIdx.x;
    const int h  = blockIdx.y;
    const int b  = blockIdx.z;
    const int qbase = qt * 128;

    const size_t base = (size_t)b * TT * DD + (size_t)h * DH;
    const float* Qg = g_q + base;
    const float* Kg = g_k + base;
    const float* Vg = g_v + base;
    float* Og = g_o + base;

    float qa[8][4];
    const int halfw = w >> 2;
    const int lrow  = (w & 3) * 16;
#pragma unroll
    for (int hf = 0; hf < 2; hf++) {
#pragma unroll
        for (int it = 0; it < 4; it++) {
            int idx = tid + it * 256;
            int r  = idx >> 4;
            int c4 = (idx & 15) << 2;
            float4 v = *(const float4*)&Qg[(size_t)(qbase + hf * 64 + r) * DD + c4];
            Ks[r][c4 + 0] = to_tf32(v.x * 0.125f);
            Ks[r][c4 + 1] = to_tf32(v.y * 0.125f);
            Ks[r][c4 + 2] = to_tf32(v.z * 0.125f);
            Ks[r][c4 + 3] = to_tf32(v.w * 0.125f);
        }
        __syncthreads();
        if (halfw == hf) {
#pragma unroll
            for (int kc = 0; kc < 8; kc++) {
                qa[kc][0] = Ks[lrow + lq    ][kc * 8 + lr    ];
                qa[kc][1] = Ks[lrow + lq + 8][kc * 8 + lr    ];
                qa[kc][2] = Ks[lrow + lq    ][kc * 8 + lr + 4];
                qa[kc][3] = Ks[lrow + lq + 8][kc * 8 + lr + 4];
            }
        }
        __syncthreads();
    }

    float m0 = -1e30f, m1 = -1e30f, l0 = 0.f, l1 = 0.f;
    float oacc[8][4];
#pragma unroll
    for (int dt = 0; dt < 8; dt++)
#pragma unroll
        for (int r = 0; r < 4; r++) oacc[dt][r] = 0.f;

    const int qrow0 = qbase + w * 16 + lq;
    const int jmax = 2 * qt + 1;

    for (int jt = 0; jt <= jmax; jt++) {
        const int kv0 = jt * 64;

        __syncthreads();
#pragma unroll
        for (int it = 0; it < 4; it++) {
            int idx = tid + it * 256;
            int r  = idx >> 4;
            int c4 = (idx & 15) << 2;
            float4 kv4 = *(const float4*)&Kg[(size_t)(kv0 + r) * DD + c4];
            Ks[r][c4 + 0] = to_tf32(kv4.x);
            Ks[r][c4 + 1] = to_tf32(kv4.y);
            Ks[r][c4 + 2] = to_tf32(kv4.z);
            Ks[r][c4 + 3] = to_tf32(kv4.w);
            float4 vv4 = *(const float4*)&Vg[(size_t)(kv0 + r) * DD + c4];
            Vs[r][c4 + 0] = to_tf32(vv4.x);
            Vs[r][c4 + 1] = to_tf32(vv4.y);
            Vs[r][c4 + 2] = to_tf32(vv4.z);
            Vs[r][c4 + 3] = to_tf32(vv4.w);
        }
        __syncthreads();

        float sa[8][4];
#pragma unroll
        for (int nt = 0; nt < 8; nt++)
#pragma unroll
            for (int r = 0; r < 4; r++) sa[nt][r] = 0.f;

#pragma unroll
        for (int kc = 0; kc < 8; kc++) {
#pragma unroll
            for (int nt = 0; nt < 8; nt++) {
                float bv[2];
                bv[0] = Ks[nt * 8 + lq][kc * 8 + lr    ];
                bv[1] = Ks[nt * 8 + lq][kc * 8 + lr + 4];
                mma_tf32(sa[nt], qa[kc], bv);
            }
        }

        if (jt >= 2 * qt) {
#pragma unroll
            for (int nt = 0; nt < 8; nt++) {
                int kc0 = kv0 + nt * 8 + 2 * lr;
                if (kc0     > qrow0)     sa[nt][0] = -1e30f;
                if (kc0 + 1 > qrow0)     sa[nt][1] = -1e30f;
                if (kc0     > qrow0 + 8) sa[nt][2] = -1e30f;
                if (kc0 + 1 > qrow0 + 8) sa[nt][3] = -1e30f;
            }
        }

        float mx0 = -1e30f, mx1 = -1e30f;
#pragma unroll
        for (int nt = 0; nt < 8; nt++) {
            mx0 = fmaxf(mx0, fmaxf(sa[nt][0], sa[nt][1]));
            mx1 = fmaxf(mx1, fmaxf(sa[nt][2], sa[nt][3]));
        }
        mx0 = fmaxf(mx0, __shfl_xor_sync(FULL, mx0, 1));
        mx0 = fmaxf(mx0, __shfl_xor_sync(FULL, mx0, 2));
        mx1 = fmaxf(mx1, __shfl_xor_sync(FULL, mx1, 1));
        mx1 = fmaxf(mx1, __shfl_xor_sync(FULL, mx1, 2));

        float nm0 = fmaxf(m0, mx0), nm1 = fmaxf(m1, mx1);
        float f0 = __expf(m0 - nm0), f1 = __expf(m1 - nm1);
        m0 = nm0; m1 = nm1;

        float s0 = 0.f, s1 = 0.f;
#pragma unroll
        for (int nt = 0; nt < 8; nt++) {
            float p0 = __expf(sa[nt][0] - nm0);
            float p1 = __expf(sa[nt][1] - nm0);
            float p2 = __expf(sa[nt][2] - nm1);
            float p3 = __expf(sa[nt][3] - nm1);
            s0 += p0 + p1;
            s1 += p2 + p3;
            sa[nt][0] = to_tf32(p0);
            sa[nt][1] = to_tf32(p1);
            sa[nt][2] = to_tf32(p2);
            sa[nt][3] = to_tf32(p3);
        }
        s0 += __shfl_xor_sync(FULL, s0, 1);
        s0 += __shfl_xor_sync(FULL, s0, 2);
        s1 += __shfl_xor_sync(FULL, s1, 1);
        s1 += __shfl_xor_sync(FULL, s1, 2);
        l0 = l0 * f0 + s0;
        l1 = l1 * f1 + s1;

#pragma unroll
        for (int dt = 0; dt < 8; dt++) {
            oacc[dt][0] *= f0;
            oacc[dt][1] *= f0;
            oacc[dt][2] *= f1;
            oacc[dt][3] *= f1;
        }

        const int src0 = (lq << 2) | (lr >> 1);
        const int src1 = src0 + 2;
        const bool odd = (lr & 1);
#pragma unroll
        for (int kc = 0; kc < 8; kc++) {
            float t00 = __shfl_sync(FULL, sa[kc][0], src0);
            float t01 = __shfl_sync(FULL, sa[kc][1], src0);
            float t10 = __shfl_sync(FULL, sa[kc][2], src0);
            float t11 = __shfl_sync(FULL, sa[kc][3], src0);
            float u00 = __shfl_sync(FULL, sa[kc][0], src1);
            float u01 = __shfl_sync(FULL, sa[kc][1], src1);
            float u10 = __shfl_sync(FULL, sa[kc][2], src1);
            float u11 = __shfl_sync(FULL, sa[kc][3], src1);
            float pa[4];
            pa[0] = odd ? t01 : t00;
            pa[1] = odd ? t11 : t10;
            pa[2] = odd ? u01 : u00;
            pa[3] = odd ? u11 : u10;
#pragma unroll
            for (int dt = 0; dt < 8; dt++) {
                float bv[2];
                bv[0] = Vs[kc * 8 + lr    ][dt * 8 + lq];
                bv[1] = Vs[kc * 8 + lr + 4][dt * 8 + lq];
                mma_tf32(oacc[dt], pa, bv);
            }
        }
    }

    const float inv0 = 1.0f / l0;
    const float inv1 = 1.0f / l1;
#pragma unroll
    for (int dt = 0; dt < 8; dt++) {
        int c = dt * 8 + 2 * lr;
        *(float2*)&Og[(size_t)qrow0 * DD + c] =
            make_float2(oacc[dt][0] * inv0, oacc[dt][1] * inv0);
        *(float2*)&Og[(size_t)(qrow0 + 8) * DD + c] =
            make_float2(oacc[dt][2] * inv1, oacc[dt][3] * inv1);
    }
}

// ---------------------------------------------------------------------------
extern "C" void kernel_launch(void* const* d_in, const int* in_sizes, int n_in,
                              void* d_out, int out_size) {
    (void)in_sizes; (void)n_in; (void)out_size;
    const float* x  = (const float*)d_in[0];
    const float* Wq = (const float*)d_in[1];
    const float* Wk = (const float*)d_in[2];
    const float* Wv = (const float*)d_in[3];
    const float* Wo = (const float*)d_in[4];
    float* out = (float*)d_out;

    qkv_kernel<<<dim3(8, 32, 3), 256>>>(x, Wq, Wk, Wv);
    flash_kernel<<<dim3(TT / 128, NH, BB), 256>>>();
    out_kernel<<<dim3(8, 32), 256>>>(Wo, out);
}

// round 5
// speedup vs baseline: 3.5620x; 1.0468x over previous
#include <cuda_runtime.h>
#include <cstdint>

// Problem constants
#define BB 2
#define TT 2048
#define DD 1024
#define NH 16
#define DH 64
#define BT (BB*TT)   // 4096

// Scratch (device globals — no allocation allowed)
__device__ float g_q[BT * DD];
__device__ float g_k[BT * DD];
__device__ float g_v[BT * DD];
__device__ float g_o[BT * DD];
__device__ float g_x[BT * DD];     // X pre-rounded to tf32
__device__ float g_wq[DD * DD];    // weights pre-rounded to tf32
__device__ float g_wk[DD * DD];
__device__ float g_wv[DD * DD];
__device__ float g_wo[DD * DD];

// ---------------------------------------------------------------------------
// TF32 / mma / ldmatrix / cp.async helpers
// ---------------------------------------------------------------------------
__device__ __forceinline__ float to_tf32(float x) {
    unsigned u;
    asm("cvt.rna.tf32.f32 %0, %1;" : "=r"(u) : "f"(x));
    return __uint_as_float(u);
}

__device__ __forceinline__ void mma_tf32(float c[4], const float a[4], const float b[2]) {
    const unsigned* A = reinterpret_cast<const unsigned*>(a);
    const unsigned* B = reinterpret_cast<const unsigned*>(b);
    asm volatile(
        "mma.sync.aligned.m16n8k8.row.col.f32.tf32.tf32.f32 "
        "{%0,%1,%2,%3}, {%4,%5,%6,%7}, {%8,%9}, {%0,%1,%2,%3};\n"
        : "+f"(c[0]), "+f"(c[1]), "+f"(c[2]), "+f"(c[3])
        : "r"(A[0]), "r"(A[1]), "r"(A[2]), "r"(A[3]), "r"(B[0]), "r"(B[1]));
}

__device__ __forceinline__ void mma_tf32_u(float c[4], const unsigned a[4], const float b[2]) {
    const unsigned* B = reinterpret_cast<const unsigned*>(b);
    asm volatile(
        "mma.sync.aligned.m16n8k8.row.col.f32.tf32.tf32.f32 "
        "{%0,%1,%2,%3}, {%4,%5,%6,%7}, {%8,%9}, {%0,%1,%2,%3};\n"
        : "+f"(c[0]), "+f"(c[1]), "+f"(c[2]), "+f"(c[3])
        : "r"(a[0]), "r"(a[1]), "r"(a[2]), "r"(a[3]), "r"(B[0]), "r"(B[1]));
}

__device__ __forceinline__ void ldsm4(unsigned r[4], const void* p) {
    unsigned a = (unsigned)__cvta_generic_to_shared(p);
    asm volatile("ldmatrix.sync.aligned.m8n8.x4.shared.b16 {%0,%1,%2,%3}, [%4];"
                 : "=r"(r[0]), "=r"(r[1]), "=r"(r[2]), "=r"(r[3]) : "r"(a));
}

__device__ __forceinline__ void cp_async16(void* sdst, const void* gsrc) {
    unsigned s = (unsigned)__cvta_generic_to_shared(sdst);
    asm volatile("cp.async.cg.shared.global [%0], [%1], 16;\n" :: "r"(s), "l"(gsrc));
}
#define CP_COMMIT()  asm volatile("cp.async.commit_group;\n" ::: "memory")
#define CP_WAIT(n)   asm volatile("cp.async.wait_group %0;\n" :: "n"(n) : "memory")

// ---------------------------------------------------------------------------
// Pre-pass: round fp32 -> tf32 in place (src -> scratch), float4 granularity
// ---------------------------------------------------------------------------
__global__ void cvt_x_kernel(const float* __restrict__ src) {
    int i = blockIdx.x * 256 + threadIdx.x;        // 1,048,576 float4s
    float4 v = ((const float4*)src)[i];
    v.x = to_tf32(v.x); v.y = to_tf32(v.y);
    v.z = to_tf32(v.z); v.w = to_tf32(v.w);
    ((float4*)g_x)[i] = v;
}

__global__ void cvt_w_kernel(const float* __restrict__ wq, const float* __restrict__ wk,
                             const float* __restrict__ wv, const float* __restrict__ wo) {
    const float* src = (blockIdx.y == 0) ? wq : (blockIdx.y == 1) ? wk
                     : (blockIdx.y == 2) ? wv : wo;
    float* dst = (blockIdx.y == 0) ? g_wq : (blockIdx.y == 1) ? g_wk
               : (blockIdx.y == 2) ? g_wv : g_wo;
    int i = blockIdx.x * 256 + threadIdx.x;        // 262,144 float4s
    float4 v = ((const float4*)src)[i];
    v.x = to_tf32(v.x); v.y = to_tf32(v.y);
    v.z = to_tf32(v.z); v.w = to_tf32(v.w);
    ((float4*)dst)[i] = v;
}

// ---------------------------------------------------------------------------
// TF32 GEMM v4: cp.async 3-stage pipeline, no conversions in loop.
// C[4096,1024] = A[4096,1024] @ W[1024,1024], both operands pre-tf32.
// 128x128 block, GK=16, 256 threads, 8 warps (2M x 4N), ldmatrix A-frags.
// A smem: [128][16] fp32, unit swizzle u^((row>>1)&3).
// B smem: [16][128] fp32, unit swizzle u^(row&3) (store conflict-free,
//         frag loads 2-way).
// Epilogue MODE: 0 = plain, 1 = tf32-round, 2 = *0.125 then tf32-round.
// ---------------------------------------------------------------------------
#define GM 128
#define GN 128
#define GK 16
#define STAGES 3

__device__ __forceinline__ void gemm_cp(const float* __restrict__ A,
                                        const float* __restrict__ W,
                                        float* __restrict__ C, int mode) {
    constexpr int N = 1024, K = 1024;
    __shared__ float As[STAGES][GM * GK];   // 8KB per stage
    __shared__ float Bs[STAGES][GK * GN];   // 8KB per stage (total 48KB exact)

    const int tid  = threadIdx.x;
    const int lane = tid & 31;
    const int warp = tid >> 5;
    const int warp_m = warp & 1;
    const int warp_n = warp >> 1;
    const int rb = blockIdx.y * GM;
    const int cb = blockIdx.x * GN;
    const int lq = lane >> 2;
    const int lr = lane & 3;

    const int ar = tid >> 2;            // A row (0..63; +64)
    const int au = tid & 3;             // A 16B unit in row
    const int bk = tid >> 5;            // B k-row (0..7; +8)
    const int bu = tid & 31;            // B 16B unit in row

    float acc[4][4][4];
#pragma unroll
    for (int i = 0; i < 4; i++)
#pragma unroll
        for (int j = 0; j < 4; j++)
#pragma unroll
            for (int r = 0; r < 4; r++) acc[i][j][r] = 0.f;

    // stage issuer: copy k-tile `it` into smem stage `s`
    auto stage = [&](int s, int it) {
        const int k0 = it * GK;
#pragma unroll
        for (int h = 0; h < 2; h++) {
            int r = ar + h * 64;
            cp_async16(&As[s][r * GK + ((au ^ ((r >> 1) & 3)) << 2)],
                       &A[(size_t)(rb + r) * K + k0 + au * 4]);
            int kr = bk + h * 8;
            cp_async16(&Bs[s][kr * GN + ((bu ^ (kr & 3)) << 2)],
                       &W[(size_t)(k0 + kr) * N + cb + bu * 4]);
        }
    };

    stage(0, 0); CP_COMMIT();
    stage(1, 1); CP_COMMIT();

    const int mrow = warp_m * 64;
    const int nb   = warp_n * 32;
    const int lrow = lane & 15;
    const int lsel = lane >> 4;

    constexpr int ITERS = K / GK;       // 64
    for (int it = 0; it < ITERS; ++it) {
        const int buf = it % STAGES;

        CP_WAIT(1);
        __syncthreads();

#pragma unroll
        for (int kc = 0; kc < 2; kc++) {
            unsigned af[4][4];
#pragma unroll
            for (int mt = 0; mt < 4; mt++) {
                int row  = mrow + mt * 16 + lrow;
                int unit = (kc * 2 + lsel) ^ ((row >> 1) & 3);
                ldsm4(af[mt], &As[buf][row * GK + unit * 4]);
            }
            float bf[4][2];
#pragma unroll
            for (int nt = 0; nt < 4; nt++) {
                int col = nb + nt * 8 + lq;
                int r0  = kc * 8 + lr;
                int r1  = r0 + 4;
                bf[nt][0] = Bs[buf][r0 * GN + (((col >> 2) ^ (r0 & 3)) << 2) + (col & 3)];
                bf[nt][1] = Bs[buf][r1 * GN + (((col >> 2) ^ (r1 & 3)) << 2) + (col & 3)];
            }
#pragma unroll
            for (int mt = 0; mt < 4; mt++)
#pragma unroll
                for (int nt = 0; nt < 4; nt++)
                    mma_tf32_u(acc[mt][nt], af[mt], bf[nt]);
        }

        if (it + 2 < ITERS) stage((it + 2) % STAGES, it + 2);
        CP_COMMIT();                    // always commit (group accounting)
        __syncthreads();
    }

    // Epilogue
#pragma unroll
    for (int mt = 0; mt < 4; mt++) {
        int r0 = rb + warp_m * 64 + mt * 16 + lq;
#pragma unroll
        for (int nt = 0; nt < 4; nt++) {
            int c = cb + warp_n * 32 + nt * 8 + 2 * lr;
            float v0 = acc[mt][nt][0], v1 = acc[mt][nt][1];
            float v2 = acc[mt][nt][2], v3 = acc[mt][nt][3];
            if (mode == 2) {
                v0 = to_tf32(v0 * 0.125f); v1 = to_tf32(v1 * 0.125f);
                v2 = to_tf32(v2 * 0.125f); v3 = to_tf32(v3 * 0.125f);
            } else if (mode == 1) {
                v0 = to_tf32(v0); v1 = to_tf32(v1);
                v2 = to_tf32(v2); v3 = to_tf32(v3);
            }
            *(float2*)&C[(size_t)r0 * N + c]       = make_float2(v0, v1);
            *(float2*)&C[(size_t)(r0 + 8) * N + c] = make_float2(v2, v3);
        }
    }
}

__global__ __launch_bounds__(256, 2) void qkv_kernel() {
    const float* W = (blockIdx.z == 0) ? g_wq : ((blockIdx.z == 1) ? g_wk : g_wv);
    float* C = (blockIdx.z == 0) ? g_q : ((blockIdx.z == 1) ? g_k : g_v);
    gemm_cp(g_x, W, C, (blockIdx.z == 0) ? 2 : 1);
}

__global__ __launch_bounds__(256, 2) void out_kernel(float* __restrict__ out) {
    gemm_cp(g_o, g_wo, out, 0);
}

// ---------------------------------------------------------------------------
// Tensor-core flash attention (causal). Data in g_q/g_k/g_v is already
// tf32-rounded (Q pre-scaled by 0.125) -> no conversions in load path.
// K/V/Q tiles loaded via cp.async. Layouts as R3/R4 (validated).
// ---------------------------------------------------------------------------
#define KS_STRIDE 68
#define VS_STRIDE 72

__global__ __launch_bounds__(256) void flash_kernel() {
    __shared__ float Ks[64][KS_STRIDE];
    __shared__ float Vs[64][VS_STRIDE];

    const int tid  = threadIdx.x;
    const int lane = tid & 31;
    const int w    = tid >> 5;
    const int lq   = lane >> 2;
    const int lr   = lane & 3;
    const unsigned FULL = 0xffffffffu;

    const int qt = (int)gridDim.x - 1 - (int)blockIdx.x;
    const int h  = blockIdx.y;
    const int b  = blockIdx.z;
    const int qbase = qt * 128;

    const size_t base = (size_t)b * TT * DD + (size_t)h * DH;
    const float* Qg = g_q + base;
    const float* Kg = g_k + base;
    const float* Vg = g_v + base;
    float* Og = g_o + base;

    // ---- Stage Q (already scaled+rounded) through Ks; build A-frags
    float qa[8][4];
    const int halfw = w >> 2;
    const int lrow  = (w & 3) * 16;
#pragma unroll
    for (int hf = 0; hf < 2; hf++) {
#pragma unroll
        for (int it = 0; it < 4; it++) {
            int idx = tid + it * 256;
            int r  = idx >> 4;
            int c4 = (idx & 15) << 2;
            cp_async16(&Ks[r][c4], &Qg[(size_t)(qbase + hf * 64 + r) * DD + c4]);
        }
        CP_COMMIT();
        CP_WAIT(0);
        __syncthreads();
        if (halfw == hf) {
#pragma unroll
            for (int kc = 0; kc < 8; kc++) {
                qa[kc][0] = Ks[lrow + lq    ][kc * 8 + lr    ];
                qa[kc][1] = Ks[lrow + lq + 8][kc * 8 + lr    ];
                qa[kc][2] = Ks[lrow + lq    ][kc * 8 + lr + 4];
                qa[kc][3] = Ks[lrow + lq + 8][kc * 8 + lr + 4];
            }
        }
        __syncthreads();
    }

    float m0 = -1e30f, m1 = -1e30f, l0 = 0.f, l1 = 0.f;
    float oacc[8][4];
#pragma unroll
    for (int dt = 0; dt < 8; dt++)
#pragma unroll
        for (int r = 0; r < 4; r++) oacc[dt][r] = 0.f;

    const int qrow0 = qbase + w * 16 + lq;
    const int jmax = 2 * qt + 1;

    for (int jt = 0; jt <= jmax; jt++) {
        const int kv0 = jt * 64;

        __syncthreads();   // previous Ks/Vs reads complete
#pragma unroll
        for (int it = 0; it < 4; it++) {
            int idx = tid + it * 256;
            int r  = idx >> 4;
            int c4 = (idx & 15) << 2;
            cp_async16(&Ks[r][c4], &Kg[(size_t)(kv0 + r) * DD + c4]);
            cp_async16(&Vs[r][c4], &Vg[(size_t)(kv0 + r) * DD + c4]);
        }
        CP_COMMIT();
        CP_WAIT(0);
        __syncthreads();

        // ---- S = Q K^T
        float sa[8][4];
#pragma unroll
        for (int nt = 0; nt < 8; nt++)
#pragma unroll
            for (int r = 0; r < 4; r++) sa[nt][r] = 0.f;

#pragma unroll
        for (int kc = 0; kc < 8; kc++) {
#pragma unroll
            for (int nt = 0; nt < 8; nt++) {
                float bv[2];
                bv[0] = Ks[nt * 8 + lq][kc * 8 + lr    ];
                bv[1] = Ks[nt * 8 + lq][kc * 8 + lr + 4];
                mma_tf32(sa[nt], qa[kc], bv);
            }
        }

        if (jt >= 2 * qt) {
#pragma unroll
            for (int nt = 0; nt < 8; nt++) {
                int kc0 = kv0 + nt * 8 + 2 * lr;
                if (kc0     > qrow0)     sa[nt][0] = -1e30f;
                if (kc0 + 1 > qrow0)     sa[nt][1] = -1e30f;
                if (kc0     > qrow0 + 8) sa[nt][2] = -1e30f;
                if (kc0 + 1 > qrow0 + 8) sa[nt][3] = -1e30f;
            }
        }

        float mx0 = -1e30f, mx1 = -1e30f;
#pragma unroll
        for (int nt = 0; nt < 8; nt++) {
            mx0 = fmaxf(mx0, fmaxf(sa[nt][0], sa[nt][1]));
            mx1 = fmaxf(mx1, fmaxf(sa[nt][2], sa[nt][3]));
        }
        mx0 = fmaxf(mx0, __shfl_xor_sync(FULL, mx0, 1));
        mx0 = fmaxf(mx0, __shfl_xor_sync(FULL, mx0, 2));
        mx1 = fmaxf(mx1, __shfl_xor_sync(FULL, mx1, 1));
        mx1 = fmaxf(mx1, __shfl_xor_sync(FULL, mx1, 2));

        float nm0 = fmaxf(m0, mx0), nm1 = fmaxf(m1, mx1);
        float f0 = __expf(m0 - nm0), f1 = __expf(m1 - nm1);
        m0 = nm0; m1 = nm1;

        float s0 = 0.f, s1 = 0.f;
#pragma unroll
        for (int nt = 0; nt < 8; nt++) {
            float p0 = __expf(sa[nt][0] - nm0);
            float p1 = __expf(sa[nt][1] - nm0);
            float p2 = __expf(sa[nt][2] - nm1);
            float p3 = __expf(sa[nt][3] - nm1);
            s0 += p0 + p1;
            s1 += p2 + p3;
            sa[nt][0] = to_tf32(p0);
            sa[nt][1] = to_tf32(p1);
            sa[nt][2] = to_tf32(p2);
            sa[nt][3] = to_tf32(p3);
        }
        s0 += __shfl_xor_sync(FULL, s0, 1);
        s0 += __shfl_xor_sync(FULL, s0, 2);
        s1 += __shfl_xor_sync(FULL, s1, 1);
        s1 += __shfl_xor_sync(FULL, s1, 2);
        l0 = l0 * f0 + s0;
        l1 = l1 * f1 + s1;

#pragma unroll
        for (int dt = 0; dt < 8; dt++) {
            oacc[dt][0] *= f0;
            oacc[dt][1] *= f0;
            oacc[dt][2] *= f1;
            oacc[dt][3] *= f1;
        }

        // ---- O += P V
        const int src0 = (lq << 2) | (lr >> 1);
        const int src1 = src0 + 2;
        const bool odd = (lr & 1);
#pragma unroll
        for (int kc = 0; kc < 8; kc++) {
            float t00 = __shfl_sync(FULL, sa[kc][0], src0);
            float t01 = __shfl_sync(FULL, sa[kc][1], src0);
            float t10 = __shfl_sync(FULL, sa[kc][2], src0);
            float t11 = __shfl_sync(FULL, sa[kc][3], src0);
            float u00 = __shfl_sync(FULL, sa[kc][0], src1);
            float u01 = __shfl_sync(FULL, sa[kc][1], src1);
            float u10 = __shfl_sync(FULL, sa[kc][2], src1);
            float u11 = __shfl_sync(FULL, sa[kc][3], src1);
            float pa[4];
            pa[0] = odd ? t01 : t00;
            pa[1] = odd ? t11 : t10;
            pa[2] = odd ? u01 : u00;
            pa[3] = odd ? u11 : u10;
#pragma unroll
            for (int dt = 0; dt < 8; dt++) {
                float bv[2];
                bv[0] = Vs[kc * 8 + lr    ][dt * 8 + lq];
                bv[1] = Vs[kc * 8 + lr + 4][dt * 8 + lq];
                mma_tf32(oacc[dt], pa, bv);
            }
        }
    }

    // ---- Epilogue: normalize, round to tf32 (consumed by out GEMM), store
    const float inv0 = 1.0f / l0;
    const float inv1 = 1.0f / l1;
#pragma unroll
    for (int dt = 0; dt < 8; dt++) {
        int c = dt * 8 + 2 * lr;
        *(float2*)&Og[(size_t)qrow0 * DD + c] =
            make_float2(to_tf32(oacc[dt][0] * inv0), to_tf32(oacc[dt][1] * inv0));
        *(float2*)&Og[(size_t)(qrow0 + 8) * DD + c] =
            make_float2(to_tf32(oacc[dt][2] * inv1), to_tf32(oacc[dt][3] * inv1));
    }
}

// ---------------------------------------------------------------------------
extern "C" void kernel_launch(void* const* d_in, const int* in_sizes, int n_in,
                              void* d_out, int out_size) {
    (void)in_sizes; (void)n_in; (void)out_size;
    const float* x  = (const float*)d_in[0];
    const float* Wq = (const float*)d_in[1];
    const float* Wk = (const float*)d_in[2];
    const float* Wv = (const float*)d_in[3];
    const float* Wo = (const float*)d_in[4];
    float* out = (float*)d_out;

    cvt_x_kernel<<<4096, 256>>>(x);
    cvt_w_kernel<<<dim3(1024, 4), 256>>>(Wq, Wk, Wv, Wo);
    qkv_kernel<<<dim3(8, 32, 3), 256>>>();
    flash_kernel<<<dim3(TT / 128, NH, BB), 256>>>();
    out_kernel<<<dim3(8, 32), 256>>>(out);
}